// round 4
// baseline (speedup 1.0000x reference)
#include <cuda_runtime.h>
#include <math.h>

#define SS 2048
#define BB 64
#define II 512
#define HH 512
#define G3 1536   // 3*H
#define LL 2
#define NBLK 128  // persistent scan CTAs (<= 148 SMs, 1 CTA/SM -> all co-resident)

// ---- Scratch (allocation-free rule: __device__ globals) --------------------
__device__ float  g_xlin [(size_t)SS * BB * G3];  // [S,B,3H] GEMM output
__device__ float  g_xlinT[(size_t)SS * G3 * BB];  // [S,3H,B] transposed
__device__ float  g_ys1  [(size_t)SS * BB * HH];  // layer-1 outputs [S,B,H]
__device__ float4 g_hbuf [2 * (HH / 4) * BB];     // ping-pong h, layout [k4][b] float4
__device__ unsigned g_bar_count = 0;              // grid barrier state (self-restoring)
__device__ unsigned g_bar_gen   = 0;

// ---------------------------------------------------------------------------
// C[M,1536] = A[M,512] @ W[1536,512]^T + bias   (M = S*B = 131072)
// 128x128x16 smem-tiled fp32 SGEMM, 256 threads, 8x8 per thread.
// ---------------------------------------------------------------------------
__global__ __launch_bounds__(256, 2) void sgemm_xlin(
    const float* __restrict__ A,
    const float* __restrict__ W,
    const float* __restrict__ bias,
    float* __restrict__ C)
{
    const int K = 512, N = 1536;
    __shared__ float As[16][132];
    __shared__ float Bs[16][132];

    int tid = threadIdx.x;
    int m0 = blockIdx.y * 128;
    int n0 = blockIdx.x * 128;
    int mf = (tid >> 4) * 8;
    int nf = (tid & 15) * 8;

    float acc[8][8];
#pragma unroll
    for (int i = 0; i < 8; i++)
#pragma unroll
        for (int j = 0; j < 8; j++) acc[i][j] = 0.f;

    for (int k0 = 0; k0 < K; k0 += 16) {
#pragma unroll
        for (int v = 0; v < 2; v++) {
            int fi = tid + v * 256;
            int r  = fi >> 2;
            int kq = (fi & 3) << 2;
            float4 a = *reinterpret_cast<const float4*>(A + (size_t)(m0 + r) * K + (k0 + kq));
            As[kq + 0][r] = a.x; As[kq + 1][r] = a.y; As[kq + 2][r] = a.z; As[kq + 3][r] = a.w;
            float4 b = *reinterpret_cast<const float4*>(W + (size_t)(n0 + r) * K + (k0 + kq));
            Bs[kq + 0][r] = b.x; Bs[kq + 1][r] = b.y; Bs[kq + 2][r] = b.z; Bs[kq + 3][r] = b.w;
        }
        __syncthreads();
#pragma unroll
        for (int k = 0; k < 16; k++) {
            float a[8], b[8];
            *(float4*)&a[0] = *(const float4*)&As[k][mf];
            *(float4*)&a[4] = *(const float4*)&As[k][mf + 4];
            *(float4*)&b[0] = *(const float4*)&Bs[k][nf];
            *(float4*)&b[4] = *(const float4*)&Bs[k][nf + 4];
#pragma unroll
            for (int i = 0; i < 8; i++)
#pragma unroll
                for (int j = 0; j < 8; j++) acc[i][j] += a[i] * b[j];
        }
        __syncthreads();
    }

#pragma unroll
    for (int i = 0; i < 8; i++) {
        float* crow = C + (size_t)(m0 + mf + i) * N + (n0 + nf);
#pragma unroll
        for (int j = 0; j < 8; j += 4) {
            float4 o;
            o.x = acc[i][j + 0] + bias[n0 + nf + j + 0];
            o.y = acc[i][j + 1] + bias[n0 + nf + j + 1];
            o.z = acc[i][j + 2] + bias[n0 + nf + j + 2];
            o.w = acc[i][j + 3] + bias[n0 + nf + j + 3];
            *reinterpret_cast<float4*>(crow + j) = o;
        }
    }
}

// ---------------------------------------------------------------------------
// Transpose x_lin [S*B, 3H] -> [S, 3H, B]  (both sides coalesced via smem tile)
// block (32,8), grid (G3/32, S*B/32). 64 % 32 == 0 so each m-tile is one s.
// ---------------------------------------------------------------------------
__global__ __launch_bounds__(256) void transpose_xlin(
    const float* __restrict__ in, float* __restrict__ out)
{
    __shared__ float t[32][33];
    int n0 = blockIdx.x * 32;
    int m0 = blockIdx.y * 32;
    int tx = threadIdx.x, ty = threadIdx.y;

#pragma unroll
    for (int r = 0; r < 4; r++)
        t[ty + r * 8][tx] = in[(size_t)(m0 + ty + r * 8) * G3 + n0 + tx];
    __syncthreads();

    int s  = m0 >> 6;
    int b0 = m0 & 63;
#pragma unroll
    for (int r = 0; r < 4; r++)
        out[((size_t)s * G3 + n0 + ty + r * 8) * BB + b0 + tx] = t[tx][ty + r * 8];
}

// ---------------------------------------------------------------------------
// Grid barrier (sense via generation counter; count self-resets each use)
// ---------------------------------------------------------------------------
__device__ __forceinline__ void grid_barrier()
{
    __syncthreads();
    if (threadIdx.x == 0) {
        unsigned gen = *(volatile unsigned*)&g_bar_gen;  // MUST read before arriving
        __threadfence();
        unsigned t = atomicAdd(&g_bar_count, 1u);
        if (t == NBLK - 1) {
            g_bar_count = 0;               // safe: nobody re-arrives until gen bumps
            __threadfence();
            atomicAdd(&g_bar_gen, 1u);
        } else {
            while (*(volatile unsigned*)&g_bar_gen == gen) { }
        }
        __threadfence();
    }
    __syncthreads();
}

__device__ __forceinline__ float sigmoidf_(float x) {
    return 1.0f / (1.0f + expf(-x));
}

// ---------------------------------------------------------------------------
// Persistent scan for one layer: 2048 GRU steps inside one kernel.
// Grid = 128 CTAs x 256 threads. CTA owns 4 H-columns; warp w: col=cl(w>>1),
// batch-half (w&1); lane = batch. Weight slice (24KB) resident in SMEM for
// the whole layer. h exchanged via gmem ping-pong in [k4][b] float4 layout
// (flat coalesced gmem copy, conflict-free smem on both sides).
// Dynamic smem: wS 1536 float4 + hS 8192 float4 = 152 KB.
// ---------------------------------------------------------------------------
__global__ __launch_bounds__(256, 1) void scan_layer(
    const float* __restrict__ xlT,    // [S, 3H, B]
    const float* __restrict__ whh_l,  // [3H, H]
    const float* __restrict__ bhh_l,  // [3H]
    const float* __restrict__ h0,     // [B, H]
    float* __restrict__ ys,           // [S, B, H]
    float* __restrict__ hfin)         // [B, H]
{
    extern __shared__ float4 sm4[];
    float4* wS = sm4;            // [4 cols][3 gates][128 k4]
    float4* hS = sm4 + 1536;     // [128 k4][64 b]

    int tid  = threadIdx.x;
    int lane = tid & 31;
    int w    = tid >> 5;
    int cl   = w >> 1;
    int b    = (w & 1) * 32 + lane;
    int col  = blockIdx.x * 4 + cl;

    // Load weight slice once: f = cl*384 + g*128 + kk
#pragma unroll
    for (int j = 0; j < 6; j++) {
        int f  = tid + j * 256;
        int c  = f / 384;
        int g  = (f >> 7) % 3;
        int kk = f & 127;
        wS[f] = *reinterpret_cast<const float4*>(
            whh_l + ((size_t)g * HH + blockIdx.x * 4 + c) * HH + kk * 4);
    }

    float bR = bhh_l[col];
    float bZ = bhh_l[HH + col];
    float bN = bhh_l[2 * HH + col];

    const float4* wr = wS + cl * 384;
    const float4* wz = wr + 128;
    const float4* wn = wr + 256;

    for (int s = 0; s < SS; s++) {
        // ---- load h_prev into smem ----
        if (s == 0) {
#pragma unroll
            for (int j = 0; j < 32; j++) {
                int f  = tid + j * 256;
                int bb = f & 63;
                int k4 = f >> 6;
                hS[k4 * 64 + bb] = *reinterpret_cast<const float4*>(h0 + bb * HH + k4 * 4);
            }
        } else {
            const float4* src = g_hbuf + ((s - 1) & 1) * 8192;
#pragma unroll
            for (int j = 0; j < 32; j++) {
                int f = tid + j * 256;
                hS[f] = src[f];
            }
        }
        __syncthreads();

        // ---- 3 dot products of length 512 ----
        float aR = 0.f, aZ = 0.f, aN = 0.f;
#pragma unroll 4
        for (int kk = 0; kk < 128; kk++) {
            float4 h  = hS[kk * 64 + b];
            float4 r4 = wr[kk];
            float4 z4 = wz[kk];
            float4 n4 = wn[kk];
            aR += r4.x * h.x + r4.y * h.y + r4.z * h.z + r4.w * h.w;
            aZ += z4.x * h.x + z4.y * h.y + z4.z * h.z + z4.w * h.w;
            aN += n4.x * h.x + n4.y * h.y + n4.z * h.z + n4.w * h.w;
        }

        // ---- gates ----
        const float* xp = xlT + (size_t)s * G3 * BB;
        float xr = xp[(size_t)col * BB + b];
        float xz = xp[(size_t)(HH + col) * BB + b];
        float xn = xp[(size_t)(2 * HH + col) * BB + b];

        float r  = sigmoidf_(xr + aR + bR);
        float z  = sigmoidf_(xz + aZ + bZ);
        float n  = tanhf(xn + r * (aN + bN));
        float hp = reinterpret_cast<const float*>(&hS[(col >> 2) * 64 + b])[col & 3];
        float hn = (1.f - z) * n + z * hp;

        // ---- write h_new + outputs ----
        float* dst = reinterpret_cast<float*>(g_hbuf + (s & 1) * 8192);
        dst[((col >> 2) * 64 + b) * 4 + (col & 3)] = hn;
        ys[((size_t)s * BB + b) * HH + col] = hn;
        if (s == SS - 1) hfin[b * HH + col] = hn;

        grid_barrier();   // h_new visible everywhere before next step's load
    }
}

// ---------------------------------------------------------------------------
extern "C" void kernel_launch(void* const* d_in, const int* in_sizes, int n_in,
                              void* d_out, int out_size)
{
    const float* x   = (const float*)d_in[0];   // [S,B,I]
    const float* hx  = (const float*)d_in[1];   // [L,B,H]
    const float* wih = (const float*)d_in[2];   // [L,3H,I]
    const float* whh = (const float*)d_in[3];   // [L,3H,H]
    const float* bih = (const float*)d_in[4];   // [L,3H]
    const float* bhh = (const float*)d_in[5];   // [L,3H]

    float* out    = (float*)d_out;                 // output [S,B,H]
    float* hidden = out + (size_t)SS * BB * HH;    // hidden [L,B,H]

    float *p_xlin, *p_xlinT, *p_ys1;
    cudaGetSymbolAddress((void**)&p_xlin,  g_xlin);
    cudaGetSymbolAddress((void**)&p_xlinT, g_xlinT);
    cudaGetSymbolAddress((void**)&p_ys1,   g_ys1);

    static int attr_done = 0;
    if (!attr_done) {
        cudaFuncSetAttribute(scan_layer,
                             cudaFuncAttributeMaxDynamicSharedMemorySize,
                             (1536 + 8192) * sizeof(float4));
        attr_done = 1;
    }

    dim3 ggrid(G3 / 128, (SS * BB) / 128);     // (12, 1024)
    dim3 tgrid(G3 / 32, (SS * BB) / 32);       // (48, 4096)
    dim3 tblk(32, 8);

    for (int l = 0; l < LL; l++) {
        const float* A  = (l == 0) ? x : p_ys1;
        float*       ys = (l == 0) ? p_ys1 : out;

        sgemm_xlin<<<ggrid, 256>>>(A,
                                   wih + (size_t)l * G3 * II,
                                   bih + (size_t)l * G3,
                                   p_xlin);

        transpose_xlin<<<tgrid, tblk>>>(p_xlin, p_xlinT);

        scan_layer<<<NBLK, 256, (1536 + 8192) * sizeof(float4)>>>(
            p_xlinT,
            whh + (size_t)l * G3 * HH,
            bhh + (size_t)l * G3,
            hx  + (size_t)l * BB * HH,
            ys,
            hidden + (size_t)l * BB * HH);
    }
}

// round 6
// speedup vs baseline: 1.1498x; 1.1498x over previous
#include <cuda_runtime.h>
#include <cuda_bf16.h>
#include <math.h>

#define SS 2048
#define BB 64
#define II 512
#define HH 512
#define G3 1536   // 3*H
#define LL 2
#define NBLK 128  // persistent scan CTAs

// ---- Scratch (allocation-free rule: __device__ globals) --------------------
__device__ float  g_xlin [(size_t)SS * BB * G3];   // [S,B,3H]
__device__ float  g_xlinT[(size_t)SS * G3 * BB];   // [S,3H,B]
__device__ float  g_ys1  [(size_t)SS * BB * HH];   // layer-1 outputs
__device__ float4 g_hbuf [2 * (HH / 4) * BB];      // ping-pong h, [k4][b] float4
__device__ __nv_bfloat16 g_ahi[(size_t)SS * BB * II];
__device__ __nv_bfloat16 g_alo[(size_t)SS * BB * II];
__device__ __nv_bfloat16 g_whi[(size_t)G3 * II];
__device__ __nv_bfloat16 g_wlo[(size_t)G3 * II];
__device__ unsigned g_bar_count = 0;
__device__ unsigned g_bar_gen   = 0;

// ---------------------------------------------------------------------------
// Split fp32 -> bf16 hi + lo residual
// ---------------------------------------------------------------------------
__global__ void split_bf16(const float* __restrict__ in,
                           __nv_bfloat16* __restrict__ hi,
                           __nv_bfloat16* __restrict__ lo, size_t n)
{
    size_t i = (size_t)blockIdx.x * blockDim.x + threadIdx.x;
    if (i < n) {
        float v = in[i];
        __nv_bfloat16 h = __float2bfloat16(v);
        hi[i] = h;
        lo[i] = __float2bfloat16(v - __bfloat162float(h));
    }
}

// ---------------------------------------------------------------------------
// C[M,1536] = A[M,512] @ W[1536,512]^T + bias, bf16x3 split via mma.sync.
// BM=128, BN=64, BK=32, 256 threads (8 warps: 4m x 2n), warp tile 32x32.
// ---------------------------------------------------------------------------
#define BM 128
#define BN 64
#define BK 32
#define LDT 40   // padded smem row stride (bf16 elems): 80B, 16B-aligned, cf ldmatrix

__device__ __forceinline__ void mma_bf16(float* d, const unsigned* a, const unsigned* b)
{
    asm volatile(
        "mma.sync.aligned.m16n8k16.row.col.f32.bf16.bf16.f32 "
        "{%0,%1,%2,%3},{%4,%5,%6,%7},{%8,%9},{%0,%1,%2,%3};"
        : "+f"(d[0]), "+f"(d[1]), "+f"(d[2]), "+f"(d[3])
        : "r"(a[0]), "r"(a[1]), "r"(a[2]), "r"(a[3]), "r"(b[0]), "r"(b[1]));
}

__device__ __forceinline__ void ldmx4(unsigned* r, const __nv_bfloat16* p)
{
    unsigned addr = (unsigned)__cvta_generic_to_shared(p);
    asm volatile("ldmatrix.sync.aligned.m8n8.x4.shared.b16 {%0,%1,%2,%3}, [%4];"
                 : "=r"(r[0]), "=r"(r[1]), "=r"(r[2]), "=r"(r[3]) : "r"(addr));
}

__global__ __launch_bounds__(256, 2) void gemm_bf16x3(
    const __nv_bfloat16* __restrict__ Ahi, const __nv_bfloat16* __restrict__ Alo,
    const __nv_bfloat16* __restrict__ Whi, const __nv_bfloat16* __restrict__ Wlo,
    const float* __restrict__ bias, float* __restrict__ C)
{
    __shared__ __align__(16) __nv_bfloat16 sA[2][BM * LDT];
    __shared__ __align__(16) __nv_bfloat16 sB[2][BN * LDT];

    int tid  = threadIdx.x;
    int m0   = blockIdx.y * BM;
    int n0   = blockIdx.x * BN;
    int w    = tid >> 5, lane = tid & 31;
    int wm   = w >> 1,   wn   = w & 1;

    float acc[2][4][4];
#pragma unroll
    for (int i = 0; i < 2; i++)
#pragma unroll
        for (int j = 0; j < 4; j++)
#pragma unroll
            for (int k = 0; k < 4; k++) acc[i][j][k] = 0.f;

    for (int k0 = 0; k0 < II; k0 += BK) {
        __syncthreads();   // prior mma done reading smem
        // A tiles: 512 uint4 per matrix (128 rows x 4 uint4)
#pragma unroll
        for (int v = 0; v < 2; v++) {
            int fi = tid + v * 256;
            int r  = fi >> 2, kq = fi & 3;
            const uint4* gh = reinterpret_cast<const uint4*>(Ahi + (size_t)(m0 + r) * II + k0);
            const uint4* gl = reinterpret_cast<const uint4*>(Alo + (size_t)(m0 + r) * II + k0);
            reinterpret_cast<uint4*>(&sA[0][(size_t)r * LDT])[kq] = gh[kq];
            reinterpret_cast<uint4*>(&sA[1][(size_t)r * LDT])[kq] = gl[kq];
        }
        // B tiles: 256 uint4 per matrix
        {
            int r = tid >> 2, kq = tid & 3;
            const uint4* gh = reinterpret_cast<const uint4*>(Whi + (size_t)(n0 + r) * II + k0);
            const uint4* gl = reinterpret_cast<const uint4*>(Wlo + (size_t)(n0 + r) * II + k0);
            reinterpret_cast<uint4*>(&sB[0][(size_t)r * LDT])[kq] = gh[kq];
            reinterpret_cast<uint4*>(&sB[1][(size_t)r * LDT])[kq] = gl[kq];
        }
        __syncthreads();

#pragma unroll
        for (int kh = 0; kh < 2; kh++) {
            int koff = kh * 16;
            unsigned af[2][2][4];   // [mtile][hi/lo][4]
            unsigned bf[4][2][2];   // [ntile][hi/lo][2]
            int q = lane >> 3, lr = lane & 7;
#pragma unroll
            for (int mt = 0; mt < 2; mt++) {
                const __nv_bfloat16* pa =
                    &sA[0][(size_t)(wm * 32 + mt * 16 + (q & 1) * 8 + lr) * LDT + koff + (q >> 1) * 8];
                ldmx4(af[mt][0], pa);
                ldmx4(af[mt][1], pa + BM * LDT);   // lo matrix
            }
#pragma unroll
            for (int j = 0; j < 2; j++) {
                int ntile = 2 * j + (q >> 1);
                const __nv_bfloat16* pb =
                    &sB[0][(size_t)(wn * 32 + ntile * 8 + lr) * LDT + koff + (q & 1) * 8];
                unsigned t[4];
                ldmx4(t, pb);
                bf[2 * j][0][0] = t[0]; bf[2 * j][0][1] = t[1];
                bf[2 * j + 1][0][0] = t[2]; bf[2 * j + 1][0][1] = t[3];
                ldmx4(t, pb + BN * LDT);
                bf[2 * j][1][0] = t[0]; bf[2 * j][1][1] = t[1];
                bf[2 * j + 1][1][0] = t[2]; bf[2 * j + 1][1][1] = t[3];
            }
#pragma unroll
            for (int mt = 0; mt < 2; mt++)
#pragma unroll
                for (int nt = 0; nt < 4; nt++) {
                    mma_bf16(acc[mt][nt], af[mt][0], bf[nt][0]);  // hi*hi
                    mma_bf16(acc[mt][nt], af[mt][0], bf[nt][1]);  // hi*lo
                    mma_bf16(acc[mt][nt], af[mt][1], bf[nt][0]);  // lo*hi
                }
        }
    }

    // Epilogue
#pragma unroll
    for (int mt = 0; mt < 2; mt++)
#pragma unroll
        for (int nt = 0; nt < 4; nt++) {
            int row = m0 + wm * 32 + mt * 16 + (lane >> 2);
            int col = n0 + wn * 32 + nt * 8 + (lane & 3) * 2;
            float b0 = bias[col], b1 = bias[col + 1];
            float2 o0 = {acc[mt][nt][0] + b0, acc[mt][nt][1] + b1};
            float2 o1 = {acc[mt][nt][2] + b0, acc[mt][nt][3] + b1};
            *reinterpret_cast<float2*>(C + (size_t)row * G3 + col) = o0;
            *reinterpret_cast<float2*>(C + (size_t)(row + 8) * G3 + col) = o1;
        }
}

// ---------------------------------------------------------------------------
// Transpose x_lin [S*B, 3H] -> [S, 3H, B]
// ---------------------------------------------------------------------------
__global__ __launch_bounds__(256) void transpose_xlin(
    const float* __restrict__ in, float* __restrict__ out)
{
    __shared__ float t[32][33];
    int n0 = blockIdx.x * 32;
    int m0 = blockIdx.y * 32;
    int tx = threadIdx.x, ty = threadIdx.y;

#pragma unroll
    for (int r = 0; r < 4; r++)
        t[ty + r * 8][tx] = in[(size_t)(m0 + ty + r * 8) * G3 + n0 + tx];
    __syncthreads();

    int s  = m0 >> 6;
    int b0 = m0 & 63;
#pragma unroll
    for (int r = 0; r < 4; r++)
        out[((size_t)s * G3 + n0 + ty + r * 8) * BB + b0 + tx] = t[tx][ty + r * 8];
}

// ---------------------------------------------------------------------------
__device__ __forceinline__ void grid_barrier()
{
    __syncthreads();
    if (threadIdx.x == 0) {
        unsigned gen = *(volatile unsigned*)&g_bar_gen;
        __threadfence();
        unsigned t = atomicAdd(&g_bar_count, 1u);
        if (t == NBLK - 1) {
            g_bar_count = 0;
            __threadfence();
            atomicAdd(&g_bar_gen, 1u);
        } else {
            while (*(volatile unsigned*)&g_bar_gen == gen) { }
        }
        __threadfence();
    }
    __syncthreads();
}

__device__ __forceinline__ float sigmoidf_(float x) { return 1.0f / (1.0f + expf(-x)); }

__device__ __forceinline__ void ffma2(unsigned long long& d,
                                      unsigned long long a, unsigned long long b)
{
    asm("fma.rn.f32x2 %0, %1, %2, %0;" : "+l"(d) : "l"(a), "l"(b));
}

// ---------------------------------------------------------------------------
// Persistent scan: 128 CTAs x 256 thr, CTA owns 4 cols.
// Thread = (cp in 2, bh in 2, kq in 2, lane): warp w = bh + 2*kq + 4*cp,
// b = bh*32+lane, cols = bid*4+cp*2+{0,1}, K-half = kq.
// Packed f32x2 FMA along K (float4 = 2 pairs, zero packing cost).
// smem: wS 24KB + hS 128KB + red 6KB.
// ---------------------------------------------------------------------------
__global__ __launch_bounds__(256, 1) void scan_layer(
    const float* __restrict__ xlT,    // [S, 3H, B]
    const float* __restrict__ whh_l,  // [3H, H]
    const float* __restrict__ bhh_l,  // [3H]
    const float* __restrict__ h0,     // [B, H]
    float* __restrict__ ys,           // [S, B, H]
    float* __restrict__ hfin)         // [B, H]
{
    extern __shared__ float4 sm4[];
    float4* wS  = sm4;                          // [4c][3g][128 k4]
    float4* hS  = sm4 + 1536;                   // [128 k4][64 b]
    float*  red = reinterpret_cast<float*>(sm4 + 1536 + 8192);  // [256][6]

    int tid  = threadIdx.x;
    int lane = tid & 31;
    int w    = tid >> 5;
    int bh   = w & 1;
    int kq   = (w >> 1) & 1;
    int cp   = w >> 2;
    int b    = bh * 32 + lane;

    // Load weight slice once: f = c*384 + g*128 + kk
#pragma unroll
    for (int j = 0; j < 6; j++) {
        int f  = tid + j * 256;
        int c  = f / 384;
        int g  = (f >> 7) % 3;
        int kk = f & 127;
        wS[f] = *reinterpret_cast<const float4*>(
            whh_l + ((size_t)g * HH + blockIdx.x * 4 + c) * HH + kk * 4);
    }

    // Biases for finalize threads (kq==0): 2 cols x 3 gates
    float bR[2], bZ[2], bN[2];
    if (kq == 0) {
#pragma unroll
        for (int cc = 0; cc < 2; cc++) {
            int col = blockIdx.x * 4 + cp * 2 + cc;
            bR[cc] = bhh_l[col];
            bZ[cc] = bhh_l[HH + col];
            bN[cc] = bhh_l[2 * HH + col];
        }
    }

    const unsigned long long* wU = reinterpret_cast<const unsigned long long*>(wS);
    const unsigned long long* hU = reinterpret_cast<const unsigned long long*>(hS);

    for (int s = 0; s < SS; s++) {
        // ---- load h_prev into smem ----
        if (s == 0) {
#pragma unroll
            for (int j = 0; j < 32; j++) {
                int f  = tid + j * 256;
                int bb = f & 63;
                int k4 = f >> 6;
                hS[k4 * 64 + bb] = *reinterpret_cast<const float4*>(h0 + bb * HH + k4 * 4);
            }
        } else {
            const float4* src = g_hbuf + ((s - 1) & 1) * 8192;
#pragma unroll
            for (int j = 0; j < 32; j++) {
                int f = tid + j * 256;
                hS[f] = src[f];
            }
        }
        __syncthreads();

        // ---- partial dots: 2 cols x 3 gates over K-half (256) ----
        unsigned long long a[6];
#pragma unroll
        for (int i = 0; i < 6; i++) a[i] = 0ull;

        int k4base = kq * 64;
#pragma unroll 8
        for (int kk = 0; kk < 64; kk++) {
            int k4 = k4base + kk;
            unsigned long long h0v = hU[(k4 * 64 + b) * 2];
            unsigned long long h1v = hU[(k4 * 64 + b) * 2 + 1];
#pragma unroll
            for (int cc = 0; cc < 2; cc++) {
                int wb = ((cp * 2 + cc) * 384 + k4) * 2;
#pragma unroll
                for (int g = 0; g < 3; g++) {
                    ffma2(a[cc * 3 + g], wU[wb + g * 256],     h0v);
                    ffma2(a[cc * 3 + g], wU[wb + g * 256 + 1], h1v);
                }
            }
        }

        // horizontal collapse + stash partials
#pragma unroll
        for (int i = 0; i < 6; i++) {
            float2 p = *reinterpret_cast<float2*>(&a[i]);
            red[tid * 6 + i] = p.x + p.y;
        }
        __syncthreads();

        // ---- finalize (kq==0 threads: 128 of them) ----
        if (kq == 0) {
            float v[6];
#pragma unroll
            for (int i = 0; i < 6; i++)
                v[i] = red[tid * 6 + i] + red[(tid + 64) * 6 + i];

            const float* xp = xlT + (size_t)s * G3 * BB;
            float* dst = reinterpret_cast<float*>(g_hbuf + (s & 1) * 8192);
#pragma unroll
            for (int cc = 0; cc < 2; cc++) {
                int col = blockIdx.x * 4 + cp * 2 + cc;
                float xr = xp[(size_t)col * BB + b];
                float xz = xp[(size_t)(HH + col) * BB + b];
                float xn = xp[(size_t)(2 * HH + col) * BB + b];
                float r  = sigmoidf_(xr + v[cc * 3 + 0] + bR[cc]);
                float z  = sigmoidf_(xz + v[cc * 3 + 1] + bZ[cc]);
                float n  = tanhf(xn + r * (v[cc * 3 + 2] + bN[cc]));
                float hp = reinterpret_cast<const float*>(hS)[((col >> 2) * 64 + b) * 4 + (col & 3)];
                float hn = (1.f - z) * n + z * hp;
                dst[((col >> 2) * 64 + b) * 4 + (col & 3)] = hn;
                ys[((size_t)s * BB + b) * HH + col] = hn;
                if (s == SS - 1) hfin[b * HH + col] = hn;
            }
        }

        grid_barrier();
    }
}

// ---------------------------------------------------------------------------
extern "C" void kernel_launch(void* const* d_in, const int* in_sizes, int n_in,
                              void* d_out, int out_size)
{
    const float* x   = (const float*)d_in[0];
    const float* hx  = (const float*)d_in[1];
    const float* wih = (const float*)d_in[2];
    const float* whh = (const float*)d_in[3];
    const float* bih = (const float*)d_in[4];
    const float* bhh = (const float*)d_in[5];

    float* out    = (float*)d_out;
    float* hidden = out + (size_t)SS * BB * HH;

    float *p_xlin, *p_xlinT, *p_ys1;
    __nv_bfloat16 *p_ahi, *p_alo, *p_whi, *p_wlo;
    cudaGetSymbolAddress((void**)&p_xlin,  g_xlin);
    cudaGetSymbolAddress((void**)&p_xlinT, g_xlinT);
    cudaGetSymbolAddress((void**)&p_ys1,   g_ys1);
    cudaGetSymbolAddress((void**)&p_ahi,   g_ahi);
    cudaGetSymbolAddress((void**)&p_alo,   g_alo);
    cudaGetSymbolAddress((void**)&p_whi,   g_whi);
    cudaGetSymbolAddress((void**)&p_wlo,   g_wlo);

    static int attr_done = 0;
    if (!attr_done) {
        cudaFuncSetAttribute(scan_layer,
                             cudaFuncAttributeMaxDynamicSharedMemorySize,
                             (1536 + 8192) * sizeof(float4) + 256 * 6 * sizeof(float));
        attr_done = 1;
    }

    const size_t nA = (size_t)SS * BB * II;
    const size_t nW = (size_t)G3 * II;
    dim3 ggrid(G3 / BN, (SS * BB) / BM);       // (24, 1024)
    dim3 tgrid(G3 / 32, (SS * BB) / 32);
    dim3 tblk(32, 8);
    size_t scan_smem = (1536 + 8192) * sizeof(float4) + 256 * 6 * sizeof(float);

    for (int l = 0; l < LL; l++) {
        const float* A  = (l == 0) ? x : p_ys1;
        float*       ys = (l == 0) ? p_ys1 : out;

        split_bf16<<<(unsigned)((nA + 255) / 256), 256>>>(A, p_ahi, p_alo, nA);
        split_bf16<<<(unsigned)((nW + 255) / 256), 256>>>(wih + (size_t)l * nW, p_whi, p_wlo, nW);

        gemm_bf16x3<<<ggrid, 256>>>(p_ahi, p_alo, p_whi, p_wlo,
                                    bih + (size_t)l * G3, p_xlin);

        transpose_xlin<<<tgrid, tblk>>>(p_xlin, p_xlinT);

        scan_layer<<<NBLK, 256, scan_smem>>>(
            p_xlinT,
            whh + (size_t)l * G3 * HH,
            bhh + (size_t)l * G3,
            hx  + (size_t)l * BB * HH,
            ys,
            hidden + (size_t)l * BB * HH);
    }
}

// round 7
// speedup vs baseline: 1.4975x; 1.3024x over previous
#include <cuda_runtime.h>
#include <cuda_bf16.h>
#include <math.h>

typedef unsigned long long ull;

#define SS 2048
#define BB 64
#define II 512
#define HH 512
#define G3 1536   // 3*H
#define LL 2
#define SCTA 128  // persistent scan CTAs

// ---- Scratch (allocation-free rule: __device__ globals) --------------------
__device__ float  g_xlin[(size_t)SS * G3 * BB];   // [S,3H,B]  (transposed natively)
__device__ float  g_T1  [(size_t)SS * HH * BB];   // [S,H,B]   ys (both layers, reused)
__device__ float4 g_hbuf[2 * (HH / 4) * BB];      // ping-pong h, [k4][b] float4
__device__ __nv_bfloat16 g_bhi[(size_t)SS * BB * II];
__device__ __nv_bfloat16 g_blo[(size_t)SS * BB * II];
__device__ __nv_bfloat16 g_whi[(size_t)G3 * II];
__device__ __nv_bfloat16 g_wlo[(size_t)G3 * II];
__device__ unsigned g_bar_count = 0;
__device__ unsigned g_bar_gen   = 0;

// ---------------------------------------------------------------------------
__global__ void split_bf16(const float* __restrict__ in,
                           __nv_bfloat16* __restrict__ hi,
                           __nv_bfloat16* __restrict__ lo, size_t n)
{
    size_t i = (size_t)blockIdx.x * blockDim.x + threadIdx.x;
    if (i < n) {
        float v = in[i];
        __nv_bfloat16 h = __float2bfloat16(v);
        hi[i] = h;
        lo[i] = __float2bfloat16(v - __bfloat162float(h));
    }
}

// ---------------------------------------------------------------------------
// xlinT[s, n, b] = sum_k W[n,k] * X[s,b,k] + bias[n]    (bf16x3 split mma)
// Per block: one s, 128 n x 64 b tile. W = MMA A-operand, x-slice = B-operand.
// BT=0: X rows [b][k] contiguous-k (natural x).  BT=1: X stored [s][k][b].
// ---------------------------------------------------------------------------
#define BMN 128  // n-tile
#define BNB 64   // b-tile (full batch)
#define BK  32
#define LDT 40   // padded smem row stride in bf16

__device__ __forceinline__ void mma_bf16(float* d, const unsigned* a, const unsigned* b)
{
    asm volatile(
        "mma.sync.aligned.m16n8k16.row.col.f32.bf16.bf16.f32 "
        "{%0,%1,%2,%3},{%4,%5,%6,%7},{%8,%9},{%0,%1,%2,%3};"
        : "+f"(d[0]), "+f"(d[1]), "+f"(d[2]), "+f"(d[3])
        : "r"(a[0]), "r"(a[1]), "r"(a[2]), "r"(a[3]), "r"(b[0]), "r"(b[1]));
}

__device__ __forceinline__ void ldmx4(unsigned* r, const __nv_bfloat16* p)
{
    unsigned addr = (unsigned)__cvta_generic_to_shared(p);
    asm volatile("ldmatrix.sync.aligned.m8n8.x4.shared.b16 {%0,%1,%2,%3}, [%4];"
                 : "=r"(r[0]), "=r"(r[1]), "=r"(r[2]), "=r"(r[3]) : "r"(addr));
}

template <int BT>
__global__ __launch_bounds__(256, 2) void gemm_xlinT(
    const __nv_bfloat16* __restrict__ Whi, const __nv_bfloat16* __restrict__ Wlo,
    const __nv_bfloat16* __restrict__ Xhi, const __nv_bfloat16* __restrict__ Xlo,
    const float* __restrict__ bias, float* __restrict__ C)
{
    __shared__ __align__(16) __nv_bfloat16 sA[2][BMN * LDT];
    __shared__ __align__(16) __nv_bfloat16 sB[2][BNB * LDT];

    int tid  = threadIdx.x;
    int s    = blockIdx.x;
    int n0   = blockIdx.y * BMN;
    int w    = tid >> 5, lane = tid & 31;
    int wm   = w >> 1,   wn   = w & 1;

    const __nv_bfloat16* Xh = Xhi + (size_t)s * BB * II;  // same offset both layouts
    const __nv_bfloat16* Xl = Xlo + (size_t)s * BB * II;

    float acc[2][4][4];
#pragma unroll
    for (int i = 0; i < 2; i++)
#pragma unroll
        for (int j = 0; j < 4; j++)
#pragma unroll
            for (int k = 0; k < 4; k++) acc[i][j][k] = 0.f;

    for (int k0 = 0; k0 < II; k0 += BK) {
        __syncthreads();
        // W tiles (A-operand): 128 rows x 32 k, hi+lo
#pragma unroll
        for (int v = 0; v < 2; v++) {
            int fi = tid + v * 256;
            int r  = fi >> 2, kq = fi & 3;
            const uint4* gh = reinterpret_cast<const uint4*>(Whi + (size_t)(n0 + r) * II + k0);
            const uint4* gl = reinterpret_cast<const uint4*>(Wlo + (size_t)(n0 + r) * II + k0);
            reinterpret_cast<uint4*>(&sA[0][(size_t)r * LDT])[kq] = gh[kq];
            reinterpret_cast<uint4*>(&sA[1][(size_t)r * LDT])[kq] = gl[kq];
        }
        // X tile (B-operand): 64 b x 32 k
        if (BT == 0) {
            int r = tid >> 2, kq = tid & 3;
            const uint4* gh = reinterpret_cast<const uint4*>(Xh + (size_t)r * II + k0);
            const uint4* gl = reinterpret_cast<const uint4*>(Xl + (size_t)r * II + k0);
            reinterpret_cast<uint4*>(&sB[0][(size_t)r * LDT])[kq] = gh[kq];
            reinterpret_cast<uint4*>(&sB[1][(size_t)r * LDT])[kq] = gl[kq];
        } else {
            // src [k][b]: load 8 b for fixed k, scatter into sB[b][k]
            int kk = tid >> 3;          // 0..31
            int bo = (tid & 7) * 8;     // 0..56
            uint4 vh = *reinterpret_cast<const uint4*>(Xh + (size_t)(k0 + kk) * BB + bo);
            uint4 vl = *reinterpret_cast<const uint4*>(Xl + (size_t)(k0 + kk) * BB + bo);
            const unsigned short* ph = reinterpret_cast<const unsigned short*>(&vh);
            const unsigned short* pl = reinterpret_cast<const unsigned short*>(&vl);
            unsigned short* s0 = reinterpret_cast<unsigned short*>(sB[0]);
            unsigned short* s1 = reinterpret_cast<unsigned short*>(sB[1]);
#pragma unroll
            for (int e = 0; e < 8; e++) {
                s0[(size_t)(bo + e) * LDT + kk] = ph[e];
                s1[(size_t)(bo + e) * LDT + kk] = pl[e];
            }
        }
        __syncthreads();

#pragma unroll
        for (int kh = 0; kh < 2; kh++) {
            int koff = kh * 16;
            unsigned af[2][2][4];
            unsigned bf[4][2][2];
            int q = lane >> 3, lr = lane & 7;
#pragma unroll
            for (int mt = 0; mt < 2; mt++) {
                const __nv_bfloat16* pa =
                    &sA[0][(size_t)(wm * 32 + mt * 16 + (q & 1) * 8 + lr) * LDT + koff + (q >> 1) * 8];
                ldmx4(af[mt][0], pa);
                ldmx4(af[mt][1], pa + BMN * LDT);
            }
#pragma unroll
            for (int j = 0; j < 2; j++) {
                int ntile = 2 * j + (q >> 1);
                const __nv_bfloat16* pb =
                    &sB[0][(size_t)(wn * 32 + ntile * 8 + lr) * LDT + koff + (q & 1) * 8];
                unsigned t[4];
                ldmx4(t, pb);
                bf[2 * j][0][0] = t[0]; bf[2 * j][0][1] = t[1];
                bf[2 * j + 1][0][0] = t[2]; bf[2 * j + 1][0][1] = t[3];
                ldmx4(t, pb + BNB * LDT);
                bf[2 * j][1][0] = t[0]; bf[2 * j][1][1] = t[1];
                bf[2 * j + 1][1][0] = t[2]; bf[2 * j + 1][1][1] = t[3];
            }
#pragma unroll
            for (int mt = 0; mt < 2; mt++)
#pragma unroll
                for (int nt = 0; nt < 4; nt++) {
                    mma_bf16(acc[mt][nt], af[mt][0], bf[nt][0]);
                    mma_bf16(acc[mt][nt], af[mt][0], bf[nt][1]);
                    mma_bf16(acc[mt][nt], af[mt][1], bf[nt][0]);
                }
        }
    }

    // Epilogue: C[(s*G3 + n)*64 + b], coalesced along b
#pragma unroll
    for (int mt = 0; mt < 2; mt++)
#pragma unroll
        for (int nt = 0; nt < 4; nt++) {
            int row  = n0 + wm * 32 + mt * 16 + (lane >> 2);
            int colb = wn * 32 + nt * 8 + (lane & 3) * 2;
            float bias0 = bias[row], bias1 = bias[row + 8];
            float2 o0 = {acc[mt][nt][0] + bias0, acc[mt][nt][1] + bias0};
            float2 o1 = {acc[mt][nt][2] + bias1, acc[mt][nt][3] + bias1};
            *reinterpret_cast<float2*>(C + ((size_t)s * G3 + row) * BB + colb) = o0;
            *reinterpret_cast<float2*>(C + ((size_t)s * G3 + row + 8) * BB + colb) = o1;
        }
}

// ---------------------------------------------------------------------------
__device__ __forceinline__ void grid_barrier()
{
    __syncthreads();
    if (threadIdx.x == 0) {
        unsigned gen = *(volatile unsigned*)&g_bar_gen;
        __threadfence();
        unsigned t = atomicAdd(&g_bar_count, 1u);
        if (t == SCTA - 1) {
            g_bar_count = 0;
            __threadfence();
            atomicAdd(&g_bar_gen, 1u);
        } else {
            while (*(volatile unsigned*)&g_bar_gen == gen) { }
        }
        __threadfence();
    }
    __syncthreads();
}

__device__ __forceinline__ float sigmoidf_(float x) { return 1.0f / (1.0f + expf(-x)); }

__device__ __forceinline__ void ffma2(ull& d, ull a, ull b)
{
    asm("fma.rn.f32x2 %0, %1, %2, %0;" : "+l"(d) : "l"(a), "l"(b));
}

__device__ __forceinline__ void cpasync16(void* dst, const void* src)
{
    unsigned d = (unsigned)__cvta_generic_to_shared(dst);
    asm volatile("cp.async.cg.shared.global [%0], [%1], 16;" :: "r"(d), "l"(src) : "memory");
}

// ---------------------------------------------------------------------------
// Persistent scan: 128 CTAs x 256 thr. CTA owns 4 cols.
// warp w: kq = w&3 (K-quarter), cp = w>>2 (colpair). Thread: 2 cols x 2 batches.
// xlT gate inputs prefetched at step start; h via cp.async; ys in [S,H,B].
// smem: wS 24KB + hS 128KB + red 13.3KB.
// ---------------------------------------------------------------------------
__global__ __launch_bounds__(256, 1) void scan_layer(
    const float* __restrict__ xlT,    // [S, 3H, B]
    const float* __restrict__ whh_l,  // [3H, H]
    const float* __restrict__ bhh_l,  // [3H]
    const float* __restrict__ h0,     // [B, H]
    float* __restrict__ ysT,          // [S, H, B]
    float* __restrict__ hfin)         // [B, H]
{
    extern __shared__ float4 sm4[];
    float4* wS  = sm4;                          // [4c][3g][128 k4]
    float4* hS  = sm4 + 1536;                   // [128 k4][64 b]
    float*  red = reinterpret_cast<float*>(sm4 + 1536 + 8192);  // [256][13]

    int tid  = threadIdx.x;
    int lane = tid & 31;
    int w    = tid >> 5;
    int kq   = w & 3;
    int cp   = w >> 2;
    int b0   = lane, b1 = lane + 32;

    // weights once: f = c*384 + g*128 + k4
#pragma unroll
    for (int j = 0; j < 6; j++) {
        int f  = tid + j * 256;
        int c  = f / 384;
        int g  = (f >> 7) % 3;
        int k4 = f & 127;
        wS[f] = *reinterpret_cast<const float4*>(
            whh_l + ((size_t)g * HH + blockIdx.x * 4 + c) * HH + k4 * 4);
    }

    float bR[2], bZ[2], bN[2];
    if (kq == 0) {
#pragma unroll
        for (int cc = 0; cc < 2; cc++) {
            int col = blockIdx.x * 4 + cp * 2 + cc;
            bR[cc] = bhh_l[col];
            bZ[cc] = bhh_l[HH + col];
            bN[cc] = bhh_l[2 * HH + col];
        }
    }

    const ull* hU = reinterpret_cast<const ull*>(hS);
    const ull* wU = reinterpret_cast<const ull*>(wS);

    for (int s = 0; s < SS; s++) {
        // ---- prefetch gate inputs (independent of h) ----
        float xg[12];
        if (kq == 0) {
            const float* xp = xlT + (size_t)s * G3 * BB;
#pragma unroll
            for (int cc = 0; cc < 2; cc++) {
                int col = blockIdx.x * 4 + cp * 2 + cc;
#pragma unroll
                for (int g = 0; g < 3; g++) {
                    xg[cc * 6 + g * 2 + 0] = __ldg(xp + (size_t)(g * HH + col) * BB + b0);
                    xg[cc * 6 + g * 2 + 1] = __ldg(xp + (size_t)(g * HH + col) * BB + b1);
                }
            }
        }

        // ---- h_prev -> smem ----
        if (s == 0) {
#pragma unroll 8
            for (int j = 0; j < 32; j++) {
                int f  = tid + j * 256;
                int bb = f & 63;
                int k4 = f >> 6;
                hS[k4 * 64 + bb] = *reinterpret_cast<const float4*>(h0 + bb * HH + k4 * 4);
            }
        } else {
            const float4* src = g_hbuf + ((s - 1) & 1) * 8192;
#pragma unroll
            for (int j = 0; j < 32; j++) {
                int f = tid + j * 256;
                cpasync16(&hS[f], &src[f]);
            }
            asm volatile("cp.async.commit_group;" ::: "memory");
            asm volatile("cp.async.wait_group 0;" ::: "memory");
        }
        __syncthreads();

        // ---- partial dots: 2 cols x 3 gates x 2 batches over K-quarter ----
        ull a[12];
#pragma unroll
        for (int i = 0; i < 12; i++) a[i] = 0ull;

        int k4base = kq * 32;
#pragma unroll 8
        for (int kk = 0; kk < 32; kk++) {
            int k4 = k4base + kk;
            ull ha0 = hU[(k4 * 64 + b0) * 2];
            ull ha1 = hU[(k4 * 64 + b0) * 2 + 1];
            ull hb0 = hU[(k4 * 64 + b1) * 2];
            ull hb1 = hU[(k4 * 64 + b1) * 2 + 1];
#pragma unroll
            for (int cc = 0; cc < 2; cc++) {
                int base = ((cp * 2 + cc) * 384 + k4) * 2;
#pragma unroll
                for (int g = 0; g < 3; g++) {
                    ull w0 = wU[base + g * 256];
                    ull w1 = wU[base + g * 256 + 1];
                    int  i0 = (cc * 3 + g) * 2;
                    ffma2(a[i0],     w0, ha0); ffma2(a[i0],     w1, ha1);
                    ffma2(a[i0 + 1], w0, hb0); ffma2(a[i0 + 1], w1, hb1);
                }
            }
        }

#pragma unroll
        for (int i = 0; i < 12; i++) {
            float2 p = *reinterpret_cast<float2*>(&a[i]);
            red[tid * 13 + i] = p.x + p.y;
        }
        __syncthreads();

        // ---- finalize (kq==0: 64 threads) ----
        if (kq == 0) {
            float v[12];
#pragma unroll
            for (int i = 0; i < 12; i++)
                v[i] = red[tid * 13 + i] + red[(tid + 32) * 13 + i]
                     + red[(tid + 64) * 13 + i] + red[(tid + 96) * 13 + i];

            float* dst = reinterpret_cast<float*>(g_hbuf + (s & 1) * 8192);
#pragma unroll
            for (int cc = 0; cc < 2; cc++) {
                int col = blockIdx.x * 4 + cp * 2 + cc;
#pragma unroll
                for (int bi = 0; bi < 2; bi++) {
                    int bb = bi ? b1 : b0;
                    float r  = sigmoidf_(xg[cc * 6 + 0 + bi] + v[(cc * 3 + 0) * 2 + bi] + bR[cc]);
                    float z  = sigmoidf_(xg[cc * 6 + 2 + bi] + v[(cc * 3 + 1) * 2 + bi] + bZ[cc]);
                    float n  = tanhf(xg[cc * 6 + 4 + bi] + r * (v[(cc * 3 + 2) * 2 + bi] + bN[cc]));
                    float hp = reinterpret_cast<const float*>(hS)[((col >> 2) * 64 + bb) * 4 + (col & 3)];
                    float hn = (1.f - z) * n + z * hp;
                    dst[((col >> 2) * 64 + bb) * 4 + (col & 3)] = hn;
                    ysT[((size_t)s * HH + col) * BB + bb] = hn;
                    if (s == SS - 1) hfin[bb * HH + col] = hn;
                }
            }
        }

        grid_barrier();
    }
}

// ---------------------------------------------------------------------------
// [S,H,B] -> [S,B,H]
// ---------------------------------------------------------------------------
__global__ __launch_bounds__(256) void transpose_out(
    const float* __restrict__ in, float* __restrict__ out)
{
    __shared__ float t[32][33];
    int s  = blockIdx.z;
    int h0 = blockIdx.x * 32;
    int b0 = blockIdx.y * 32;
    int tx = threadIdx.x, ty = threadIdx.y;

#pragma unroll
    for (int r = 0; r < 4; r++)
        t[ty + r * 8][tx] = in[((size_t)s * HH + h0 + ty + r * 8) * BB + b0 + tx];
    __syncthreads();
#pragma unroll
    for (int r = 0; r < 4; r++)
        out[((size_t)s * BB + b0 + ty + r * 8) * HH + h0 + tx] = t[tx][ty + r * 8];
}

// ---------------------------------------------------------------------------
extern "C" void kernel_launch(void* const* d_in, const int* in_sizes, int n_in,
                              void* d_out, int out_size)
{
    const float* x   = (const float*)d_in[0];
    const float* hx  = (const float*)d_in[1];
    const float* wih = (const float*)d_in[2];
    const float* whh = (const float*)d_in[3];
    const float* bih = (const float*)d_in[4];
    const float* bhh = (const float*)d_in[5];

    float* out    = (float*)d_out;
    float* hidden = out + (size_t)SS * BB * HH;

    float *p_xlin, *p_T1;
    __nv_bfloat16 *p_bhi, *p_blo, *p_whi, *p_wlo;
    cudaGetSymbolAddress((void**)&p_xlin, g_xlin);
    cudaGetSymbolAddress((void**)&p_T1,   g_T1);
    cudaGetSymbolAddress((void**)&p_bhi,  g_bhi);
    cudaGetSymbolAddress((void**)&p_blo,  g_blo);
    cudaGetSymbolAddress((void**)&p_whi,  g_whi);
    cudaGetSymbolAddress((void**)&p_wlo,  g_wlo);

    size_t scan_smem = (1536 + 8192) * sizeof(float4) + 256 * 13 * sizeof(float);
    static int attr_done = 0;
    if (!attr_done) {
        cudaFuncSetAttribute(scan_layer,
                             cudaFuncAttributeMaxDynamicSharedMemorySize, (int)scan_smem);
        attr_done = 1;
    }

    const size_t nX = (size_t)SS * BB * II;
    const size_t nW = (size_t)G3 * II;
    dim3 ggrid(SS, G3 / BMN);        // (2048, 12)
    dim3 tgrid(HH / 32, BB / 32, SS);
    dim3 tblk(32, 8);

    for (int l = 0; l < LL; l++) {
        const float* Bsrc = (l == 0) ? x : p_T1;

        split_bf16<<<(unsigned)((nW + 255) / 256), 256>>>(wih + (size_t)l * nW, p_whi, p_wlo, nW);
        split_bf16<<<(unsigned)((nX + 255) / 256), 256>>>(Bsrc, p_bhi, p_blo, nX);

        if (l == 0)
            gemm_xlinT<0><<<ggrid, 256>>>(p_whi, p_wlo, p_bhi, p_blo,
                                          bih + (size_t)l * G3, p_xlin);
        else
            gemm_xlinT<1><<<ggrid, 256>>>(p_whi, p_wlo, p_bhi, p_blo,
                                          bih + (size_t)l * G3, p_xlin);

        scan_layer<<<SCTA, 256, scan_smem>>>(
            p_xlin,
            whh + (size_t)l * G3 * HH,
            bhh + (size_t)l * G3,
            hx  + (size_t)l * BB * HH,
            p_T1,
            hidden + (size_t)l * BB * HH);
    }

    transpose_out<<<tgrid, tblk>>>(p_T1, out);
}

// round 8
// speedup vs baseline: 2.1917x; 1.4636x over previous
#include <cuda_runtime.h>
#include <cuda_bf16.h>
#include <math.h>

typedef unsigned long long ull;

#define SS 2048
#define BB 64
#define II 512
#define HH 512
#define G3 1536   // 3*H
#define LL 2

// ---- Scratch (allocation-free rule: __device__ globals) --------------------
__device__ float g_xlin[(size_t)SS * G3 * BB];   // [S,3H,B]
__device__ float g_T1  [(size_t)SS * HH * BB];   // [S,H,B] layer-1 ys
__device__ __nv_bfloat16 g_bhi[(size_t)SS * BB * II];
__device__ __nv_bfloat16 g_blo[(size_t)SS * BB * II];
__device__ __nv_bfloat16 g_whi[(size_t)G3 * II];
__device__ __nv_bfloat16 g_wlo[(size_t)G3 * II];
// h exchange: [buf 2][bg 4][16 b][512 k] bf16 hi/lo
__device__ __nv_bfloat16 g_hb_hi[2 * 4 * 16 * 512];
__device__ __nv_bfloat16 g_hb_lo[2 * 4 * 16 * 512];
// per-batchgroup monotonic counters (padded to 128B)
__device__ unsigned g_P[4 * 32];
__device__ unsigned g_C[4 * 32];

// ---------------------------------------------------------------------------
__global__ void split_bf16(const float* __restrict__ in,
                           __nv_bfloat16* __restrict__ hi,
                           __nv_bfloat16* __restrict__ lo, size_t n)
{
    size_t i = (size_t)blockIdx.x * blockDim.x + threadIdx.x;
    if (i < n) {
        float v = in[i];
        __nv_bfloat16 h = __float2bfloat16(v);
        hi[i] = h;
        lo[i] = __float2bfloat16(v - __bfloat162float(h));
    }
}

__global__ void reset_sync()
{
    if (threadIdx.x < 128) { g_P[threadIdx.x] = 0; g_C[threadIdx.x] = 0; }
}

// ---------------------------------------------------------------------------
// mma helpers
// ---------------------------------------------------------------------------
__device__ __forceinline__ void mma_bf16(float* d, const unsigned* a, const unsigned* b)
{
    asm volatile(
        "mma.sync.aligned.m16n8k16.row.col.f32.bf16.bf16.f32 "
        "{%0,%1,%2,%3},{%4,%5,%6,%7},{%8,%9},{%0,%1,%2,%3};"
        : "+f"(d[0]), "+f"(d[1]), "+f"(d[2]), "+f"(d[3])
        : "r"(a[0]), "r"(a[1]), "r"(a[2]), "r"(a[3]), "r"(b[0]), "r"(b[1]));
}

__device__ __forceinline__ void ldmx4(unsigned* r, const __nv_bfloat16* p)
{
    unsigned addr = (unsigned)__cvta_generic_to_shared(p);
    asm volatile("ldmatrix.sync.aligned.m8n8.x4.shared.b16 {%0,%1,%2,%3}, [%4];"
                 : "=r"(r[0]), "=r"(r[1]), "=r"(r[2]), "=r"(r[3]) : "r"(addr));
}

__device__ __forceinline__ void cpasync16(void* dst, const void* src)
{
    unsigned d = (unsigned)__cvta_generic_to_shared(dst);
    asm volatile("cp.async.cg.shared.global [%0], [%1], 16;" :: "r"(d), "l"(src) : "memory");
}

// ---------------------------------------------------------------------------
// xlinT[s, n, b] = sum_k W[n,k] * X[s,b,k] + bias[n]  (bf16x3 mma, unchanged)
// ---------------------------------------------------------------------------
#define BMN 128
#define BNB 64
#define BK  32
#define LDT 40

template <int BT>
__global__ __launch_bounds__(256, 2) void gemm_xlinT(
    const __nv_bfloat16* __restrict__ Whi, const __nv_bfloat16* __restrict__ Wlo,
    const __nv_bfloat16* __restrict__ Xhi, const __nv_bfloat16* __restrict__ Xlo,
    const float* __restrict__ bias, float* __restrict__ C)
{
    __shared__ __align__(16) __nv_bfloat16 sA[2][BMN * LDT];
    __shared__ __align__(16) __nv_bfloat16 sB[2][BNB * LDT];

    int tid  = threadIdx.x;
    int s    = blockIdx.x;
    int n0   = blockIdx.y * BMN;
    int w    = tid >> 5, lane = tid & 31;
    int wm   = w >> 1,   wn   = w & 1;

    const __nv_bfloat16* Xh = Xhi + (size_t)s * BB * II;
    const __nv_bfloat16* Xl = Xlo + (size_t)s * BB * II;

    float acc[2][4][4];
#pragma unroll
    for (int i = 0; i < 2; i++)
#pragma unroll
        for (int j = 0; j < 4; j++)
#pragma unroll
            for (int k = 0; k < 4; k++) acc[i][j][k] = 0.f;

    for (int k0 = 0; k0 < II; k0 += BK) {
        __syncthreads();
#pragma unroll
        for (int v = 0; v < 2; v++) {
            int fi = tid + v * 256;
            int r  = fi >> 2, kq = fi & 3;
            const uint4* gh = reinterpret_cast<const uint4*>(Whi + (size_t)(n0 + r) * II + k0);
            const uint4* gl = reinterpret_cast<const uint4*>(Wlo + (size_t)(n0 + r) * II + k0);
            reinterpret_cast<uint4*>(&sA[0][(size_t)r * LDT])[kq] = gh[kq];
            reinterpret_cast<uint4*>(&sA[1][(size_t)r * LDT])[kq] = gl[kq];
        }
        if (BT == 0) {
            int r = tid >> 2, kq = tid & 3;
            const uint4* gh = reinterpret_cast<const uint4*>(Xh + (size_t)r * II + k0);
            const uint4* gl = reinterpret_cast<const uint4*>(Xl + (size_t)r * II + k0);
            reinterpret_cast<uint4*>(&sB[0][(size_t)r * LDT])[kq] = gh[kq];
            reinterpret_cast<uint4*>(&sB[1][(size_t)r * LDT])[kq] = gl[kq];
        } else {
            int kk = tid >> 3;
            int bo = (tid & 7) * 8;
            uint4 vh = *reinterpret_cast<const uint4*>(Xh + (size_t)(k0 + kk) * BB + bo);
            uint4 vl = *reinterpret_cast<const uint4*>(Xl + (size_t)(k0 + kk) * BB + bo);
            const unsigned short* ph = reinterpret_cast<const unsigned short*>(&vh);
            const unsigned short* pl = reinterpret_cast<const unsigned short*>(&vl);
            unsigned short* s0 = reinterpret_cast<unsigned short*>(sB[0]);
            unsigned short* s1 = reinterpret_cast<unsigned short*>(sB[1]);
#pragma unroll
            for (int e = 0; e < 8; e++) {
                s0[(size_t)(bo + e) * LDT + kk] = ph[e];
                s1[(size_t)(bo + e) * LDT + kk] = pl[e];
            }
        }
        __syncthreads();

#pragma unroll
        for (int kh = 0; kh < 2; kh++) {
            int koff = kh * 16;
            unsigned af[2][2][4];
            unsigned bf[4][2][2];
            int q = lane >> 3, lr = lane & 7;
#pragma unroll
            for (int mt = 0; mt < 2; mt++) {
                const __nv_bfloat16* pa =
                    &sA[0][(size_t)(wm * 32 + mt * 16 + (q & 1) * 8 + lr) * LDT + koff + (q >> 1) * 8];
                ldmx4(af[mt][0], pa);
                ldmx4(af[mt][1], pa + BMN * LDT);
            }
#pragma unroll
            for (int j = 0; j < 2; j++) {
                int ntile = 2 * j + (q >> 1);
                const __nv_bfloat16* pb =
                    &sB[0][(size_t)(wn * 32 + ntile * 8 + lr) * LDT + koff + (q & 1) * 8];
                unsigned t[4];
                ldmx4(t, pb);
                bf[2 * j][0][0] = t[0]; bf[2 * j][0][1] = t[1];
                bf[2 * j + 1][0][0] = t[2]; bf[2 * j + 1][0][1] = t[3];
                ldmx4(t, pb + BNB * LDT);
                bf[2 * j][1][0] = t[0]; bf[2 * j][1][1] = t[1];
                bf[2 * j + 1][1][0] = t[2]; bf[2 * j + 1][1][1] = t[3];
            }
#pragma unroll
            for (int mt = 0; mt < 2; mt++)
#pragma unroll
                for (int nt = 0; nt < 4; nt++) {
                    mma_bf16(acc[mt][nt], af[mt][0], bf[nt][0]);
                    mma_bf16(acc[mt][nt], af[mt][0], bf[nt][1]);
                    mma_bf16(acc[mt][nt], af[mt][1], bf[nt][0]);
                }
        }
    }

#pragma unroll
    for (int mt = 0; mt < 2; mt++)
#pragma unroll
        for (int nt = 0; nt < 4; nt++) {
            int row  = n0 + wm * 32 + mt * 16 + (lane >> 2);
            int colb = wn * 32 + nt * 8 + (lane & 3) * 2;
            float bias0 = bias[row], bias1 = bias[row + 8];
            float2 o0 = {acc[mt][nt][0] + bias0, acc[mt][nt][1] + bias0};
            float2 o1 = {acc[mt][nt][2] + bias1, acc[mt][nt][3] + bias1};
            *reinterpret_cast<float2*>(C + ((size_t)s * G3 + row) * BB + colb) = o0;
            *reinterpret_cast<float2*>(C + ((size_t)s * G3 + row + 8) * BB + colb) = o1;
        }
}

// ---------------------------------------------------------------------------
// Persistent scan, mma-based. 128 CTAs = 32 colgroups x 4 batchgroups.
// CTA: 16 cols x 16 batches. M=48 gate-rows (g*16+c), N=16 batches, K=512.
// Warp w owns K-slice [w*64, w*64+64). A-frags (weights bf16 hi/lo) preloaded
// in registers for all 2048 steps. h exchanged via gmem bf16 hi/lo ping-pong,
// per-batchgroup flag sync (monotonic counters P/C).
// ---------------------------------------------------------------------------
#define LDW 520
#define LDH 520
#define OFF_WHI 0
#define OFF_WLO (48 * LDW * 2)
#define OFF_HHI (2 * 48 * LDW * 2)
#define OFF_HLO (OFF_HHI + 16 * LDH * 2)
#define OFF_RED (OFF_HLO + 16 * LDH * 2)
#define SCAN_SMEM (OFF_RED + 8 * 768 * 4)

__device__ __forceinline__ float sigmoidf_(float x) { return 1.0f / (1.0f + expf(-x)); }

__global__ __launch_bounds__(256, 1) void scan_layer(
    const float* __restrict__ xlT,    // [S, 3H, B]
    const float* __restrict__ whh_l,  // [3H, H]
    const float* __restrict__ bhh_l,  // [3H]
    const float* __restrict__ h0,     // [B, H]
    float* __restrict__ ysT,          // [S, H, B]
    float* __restrict__ hfin)         // [B, H]
{
    extern __shared__ char sm[];
    __nv_bfloat16* sWhi = reinterpret_cast<__nv_bfloat16*>(sm + OFF_WHI);
    __nv_bfloat16* sWlo = reinterpret_cast<__nv_bfloat16*>(sm + OFF_WLO);
    __nv_bfloat16* sHhi = reinterpret_cast<__nv_bfloat16*>(sm + OFF_HHI);
    __nv_bfloat16* sHlo = reinterpret_cast<__nv_bfloat16*>(sm + OFF_HLO);
    float*         red  = reinterpret_cast<float*>(sm + OFF_RED);

    int tid  = threadIdx.x;
    int lane = tid & 31;
    int w    = tid >> 5;
    int cg   = blockIdx.x >> 2;
    int bg   = blockIdx.x & 3;
    int q    = lane >> 3, lr = lane & 7;

    // ---- convert weight slice to bf16 hi/lo in smem (once) ----
    for (int i = tid; i < 48 * 512; i += 256) {
        int m = i >> 9, k = i & 511;
        int g = m >> 4, c = m & 15;
        float v = whh_l[((size_t)(g * 512 + cg * 16 + c)) * 512 + k];
        __nv_bfloat16 hi = __float2bfloat16(v);
        sWhi[m * LDW + k] = hi;
        sWlo[m * LDW + k] = __float2bfloat16(v - __bfloat162float(hi));
    }
    __syncthreads();

    // ---- preload A fragments (weights) into registers for whole scan ----
    unsigned afh[3][4][4], afl[3][4][4];
#pragma unroll
    for (int mt = 0; mt < 3; mt++)
#pragma unroll
        for (int kt = 0; kt < 4; kt++) {
            int idx = (mt * 16 + (q & 1) * 8 + lr) * LDW + (w * 4 + kt) * 16 + (q >> 1) * 8;
            ldmx4(afh[mt][kt], sWhi + idx);
            ldmx4(afl[mt][kt], sWlo + idx);
        }

    // ---- per-thread output ownership ----
    int c_own  = tid >> 4;
    int bl_own = tid & 15;
    int col    = cg * 16 + c_own;
    int bglob  = bg * 16 + bl_own;
    float hp = h0[(size_t)bglob * 512 + col];
    float bR = bhh_l[col], bZ = bhh_l[512 + col], bN = bhh_l[1024 + col];

    volatile unsigned* Pv = g_P + bg * 32;
    volatile unsigned* Cv = g_C + bg * 32;
    unsigned* Pa = (unsigned*)(g_P + bg * 32);
    unsigned* Ca = (unsigned*)(g_C + bg * 32);

    for (int s = 0; s < SS; s++) {
        // prefetch gate inputs (static, independent of h)
        const float* xp = xlT + ((size_t)s * G3 + col) * 64 + bglob;
        float xr = __ldg(xp);
        float xz = __ldg(xp + 512 * 64);
        float xn = __ldg(xp + 1024 * 64);

        // ---- wait for producers of h_{s-1}, then load slice ----
        if (s > 0) {
            if (tid == 0) {
                while (*Pv < 32u * (unsigned)s) { }
                __threadfence();
            }
            __syncthreads();
            const __nv_bfloat16* srcH = g_hb_hi + (size_t)((((s - 1) & 1) * 4 + bg) * 16) * 512;
            const __nv_bfloat16* srcL = g_hb_lo + (size_t)((((s - 1) & 1) * 4 + bg) * 16) * 512;
#pragma unroll
            for (int j = 0; j < 4; j++) {
                int ch = tid + j * 256;        // 0..1023
                int b  = ch >> 6, kc = ch & 63;
                cpasync16(sHhi + b * LDH + kc * 8, srcH + b * 512 + kc * 8);
                cpasync16(sHlo + b * LDH + kc * 8, srcL + b * 512 + kc * 8);
            }
            asm volatile("cp.async.commit_group;" ::: "memory");
            asm volatile("cp.async.wait_group 0;" ::: "memory");
        } else {
            for (int i = tid; i < 16 * 512; i += 256) {
                int b = i >> 9, k = i & 511;
                float v = h0[(size_t)(bg * 16 + b) * 512 + k];
                __nv_bfloat16 hi = __float2bfloat16(v);
                sHhi[b * LDH + k] = hi;
                sHlo[b * LDH + k] = __float2bfloat16(v - __bfloat162float(hi));
            }
        }
        __syncthreads();
        if (tid == 0) atomicAdd(Ca, 1u);   // this CTA finished reading hb buffer

        // ---- mma: K-slice per warp, full 48x16 accum ----
        float acc[3][2][4];
#pragma unroll
        for (int i = 0; i < 3; i++)
#pragma unroll
            for (int j = 0; j < 2; j++)
#pragma unroll
                for (int k = 0; k < 4; k++) acc[i][j][k] = 0.f;

#pragma unroll
        for (int kt = 0; kt < 4; kt++) {
            unsigned bh[4], bl4[4];
            int hidx = ((q >> 1) * 8 + lr) * LDH + (w * 4 + kt) * 16 + (q & 1) * 8;
            ldmx4(bh, sHhi + hidx);
            ldmx4(bl4, sHlo + hidx);
#pragma unroll
            for (int mt = 0; mt < 3; mt++) {
                mma_bf16(acc[mt][0], afh[mt][kt], bh);
                mma_bf16(acc[mt][0], afh[mt][kt], bl4);
                mma_bf16(acc[mt][0], afl[mt][kt], bh);
                mma_bf16(acc[mt][1], afh[mt][kt], bh + 2);
                mma_bf16(acc[mt][1], afh[mt][kt], bl4 + 2);
                mma_bf16(acc[mt][1], afl[mt][kt], bh + 2);
            }
        }

        // ---- stash per-warp partials ----
#pragma unroll
        for (int mt = 0; mt < 3; mt++)
#pragma unroll
            for (int nt = 0; nt < 2; nt++) {
                int m = mt * 16 + (lane >> 2);
                int n = nt * 8 + (lane & 3) * 2;
                *reinterpret_cast<float2*>(&red[w * 768 + m * 16 + n]) =
                    make_float2(acc[mt][nt][0], acc[mt][nt][1]);
                *reinterpret_cast<float2*>(&red[w * 768 + (m + 8) * 16 + n]) =
                    make_float2(acc[mt][nt][2], acc[mt][nt][3]);
            }
        __syncthreads();

        // ---- reduce 8 warps + gates (1 output per thread) ----
        float v0 = 0.f, v1 = 0.f, v2 = 0.f;
#pragma unroll
        for (int ww = 0; ww < 8; ww++) {
            v0 += red[ww * 768 + tid];
            v1 += red[ww * 768 + 256 + tid];
            v2 += red[ww * 768 + 512 + tid];
        }

        float r  = sigmoidf_(xr + v0 + bR);
        float z  = sigmoidf_(xz + v1 + bZ);
        float nn = tanhf(xn + r * (v2 + bN));
        float hn = (1.f - z) * nn + z * hp;
        hp = hn;

        // ---- wait consumers done with buf[s&1] (step s-1 loads) ----
        if (tid == 0) {
            while (*Cv < 32u * (unsigned)s) { }
        }
        __syncthreads();

        // ---- stores ----
        ysT[((size_t)s * 512 + col) * 64 + bglob] = hn;
        __nv_bfloat16 hb = __float2bfloat16(hn);
        size_t ho = (size_t)(((s & 1) * 4 + bg) * 16 + bl_own) * 512 + col;
        g_hb_hi[ho] = hb;
        g_hb_lo[ho] = __float2bfloat16(hn - __bfloat162float(hb));
        if (s == SS - 1) hfin[(size_t)bglob * 512 + col] = hn;

        __syncthreads();
        if (tid == 0) { __threadfence(); atomicAdd(Pa, 1u); }
    }
}

// ---------------------------------------------------------------------------
// [S,H,B] -> [S,B,H]
// ---------------------------------------------------------------------------
__global__ __launch_bounds__(256) void transpose_out(
    const float* __restrict__ in, float* __restrict__ out)
{
    __shared__ float t[32][33];
    int s  = blockIdx.z;
    int h0 = blockIdx.x * 32;
    int b0 = blockIdx.y * 32;
    int tx = threadIdx.x, ty = threadIdx.y;

#pragma unroll
    for (int r = 0; r < 4; r++)
        t[ty + r * 8][tx] = in[((size_t)s * HH + h0 + ty + r * 8) * BB + b0 + tx];
    __syncthreads();
#pragma unroll
    for (int r = 0; r < 4; r++)
        out[((size_t)s * BB + b0 + ty + r * 8) * HH + h0 + tx] = t[tx][ty + r * 8];
}

// ---------------------------------------------------------------------------
extern "C" void kernel_launch(void* const* d_in, const int* in_sizes, int n_in,
                              void* d_out, int out_size)
{
    const float* x   = (const float*)d_in[0];
    const float* hx  = (const float*)d_in[1];
    const float* wih = (const float*)d_in[2];
    const float* whh = (const float*)d_in[3];
    const float* bih = (const float*)d_in[4];
    const float* bhh = (const float*)d_in[5];

    float* out    = (float*)d_out;
    float* hidden = out + (size_t)SS * BB * HH;

    float *p_xlin, *p_T1;
    __nv_bfloat16 *p_bhi, *p_blo, *p_whi, *p_wlo;
    cudaGetSymbolAddress((void**)&p_xlin, g_xlin);
    cudaGetSymbolAddress((void**)&p_T1,   g_T1);
    cudaGetSymbolAddress((void**)&p_bhi,  g_bhi);
    cudaGetSymbolAddress((void**)&p_blo,  g_blo);
    cudaGetSymbolAddress((void**)&p_whi,  g_whi);
    cudaGetSymbolAddress((void**)&p_wlo,  g_wlo);

    static int attr_done = 0;
    if (!attr_done) {
        cudaFuncSetAttribute(scan_layer,
                             cudaFuncAttributeMaxDynamicSharedMemorySize, SCAN_SMEM);
        attr_done = 1;
    }

    const size_t nX = (size_t)SS * BB * II;
    const size_t nW = (size_t)G3 * II;
    dim3 ggrid(SS, G3 / BMN);
    dim3 tgrid(HH / 32, BB / 32, SS);
    dim3 tblk(32, 8);

    for (int l = 0; l < LL; l++) {
        const float* Bsrc = (l == 0) ? x : p_T1;

        split_bf16<<<(unsigned)((nW + 255) / 256), 256>>>(wih + (size_t)l * nW, p_whi, p_wlo, nW);
        split_bf16<<<(unsigned)((nX + 255) / 256), 256>>>(Bsrc, p_bhi, p_blo, nX);

        if (l == 0)
            gemm_xlinT<0><<<ggrid, 256>>>(p_whi, p_wlo, p_bhi, p_blo,
                                          bih + (size_t)l * G3, p_xlin);
        else
            gemm_xlinT<1><<<ggrid, 256>>>(p_whi, p_wlo, p_bhi, p_blo,
                                          bih + (size_t)l * G3, p_xlin);

        reset_sync<<<1, 128>>>();

        scan_layer<<<128, 256, SCAN_SMEM>>>(
            p_xlin,
            whh + (size_t)l * G3 * HH,
            bhh + (size_t)l * G3,
            hx  + (size_t)l * BB * HH,
            p_T1,
            hidden + (size_t)l * BB * HH);
    }

    transpose_out<<<tgrid, tblk>>>(p_T1, out);
}